// round 1
// baseline (speedup 1.0000x reference)
#include <cuda_runtime.h>
#include <math_constants.h>

#define BB 2
#define SS 2048
#define DD 512
#define HH 8
#define DHEAD 64

// Scratch (allocation-free: __device__ globals)
__device__ float g_Qh[BB * SS * DD];
__device__ float g_Kh[BB * SS * DD];
__device__ float g_Vh[BB * SS * DD];
__device__ float g_ctx[BB * SS * DD];

// ---------------------------------------------------------------------------
// GEMM: C[M,N] = A[M,K] @ W[K,N] + bias[N]
// Tile: BM=128, BN=64, BK=16. 256 threads (16x16), 8x4 micro-tile per thread.
// A tile stored transposed in smem (As[k][m], padded stride 132) so compute
// reads are LDS.128 / broadcast and conflict-light.
// ---------------------------------------------------------------------------
__global__ __launch_bounds__(256)
void gemm_bias_kernel(const float* __restrict__ A, const float* __restrict__ W,
                      const float* __restrict__ bias, float* __restrict__ C,
                      int M, int N, int K) {
    __shared__ float As[16][132];
    __shared__ float Ws[16][64];

    const int tid = threadIdx.x;
    const int ty = tid >> 4;      // 0..15 -> 8 rows each
    const int tx = tid & 15;      // 0..15 -> 4 cols each
    const int m0 = blockIdx.x * 128;
    const int n0 = blockIdx.y * 64;

    float acc[8][4];
    const float4 bv = *reinterpret_cast<const float4*>(bias + n0 + tx * 4);
#pragma unroll
    for (int i = 0; i < 8; i++) {
        acc[i][0] = bv.x; acc[i][1] = bv.y; acc[i][2] = bv.z; acc[i][3] = bv.w;
    }

    for (int k0 = 0; k0 < K; k0 += 16) {
        // Load A tile (128x16) transposed into smem. 512 float4, 2 per thread.
#pragma unroll
        for (int t = 0; t < 2; t++) {
            int idx = tid + t * 256;          // 0..511
            int r = idx >> 2;                 // 0..127
            int k4 = idx & 3;                 // 0..3
            float4 a = *reinterpret_cast<const float4*>(
                A + (size_t)(m0 + r) * K + k0 + k4 * 4);
            As[k4 * 4 + 0][r] = a.x;
            As[k4 * 4 + 1][r] = a.y;
            As[k4 * 4 + 2][r] = a.z;
            As[k4 * 4 + 3][r] = a.w;
        }
        // Load W tile (16x64) natural. 256 float4, 1 per thread.
        {
            int kk = tid >> 4;                // 0..15
            int c4 = tid & 15;                // 0..15
            float4 w = *reinterpret_cast<const float4*>(
                W + (size_t)(k0 + kk) * N + n0 + c4 * 4);
            *reinterpret_cast<float4*>(&Ws[kk][c4 * 4]) = w;
        }
        __syncthreads();

#pragma unroll
        for (int k = 0; k < 16; k++) {
            float4 a0 = *reinterpret_cast<const float4*>(&As[k][ty * 8]);
            float4 a1 = *reinterpret_cast<const float4*>(&As[k][ty * 8 + 4]);
            float4 wb = *reinterpret_cast<const float4*>(&Ws[k][tx * 4]);
            float ra[8] = {a0.x, a0.y, a0.z, a0.w, a1.x, a1.y, a1.z, a1.w};
            float rb[4] = {wb.x, wb.y, wb.z, wb.w};
#pragma unroll
            for (int i = 0; i < 8; i++)
#pragma unroll
                for (int j = 0; j < 4; j++)
                    acc[i][j] += ra[i] * rb[j];
        }
        __syncthreads();
    }

#pragma unroll
    for (int i = 0; i < 8; i++) {
        float4 o = make_float4(acc[i][0], acc[i][1], acc[i][2], acc[i][3]);
        *reinterpret_cast<float4*>(C + (size_t)(m0 + ty * 8 + i) * N + n0 + tx * 4) = o;
    }
}

// ---------------------------------------------------------------------------
// Fused flash attention with structural bias.
// Block = (q-tile of 64 rows, head h, batch b). 256 threads (16x16).
// Thread (ty,tx): 4 q-rows (ty*4..+3) x 4 cols (tx*4..+3) micro-tile for both
// the score tile and the output accumulator. Online softmax: per-row m,l kept
// replicated in registers across the 16 tx threads (shfl-reduced each tile).
// smem: Qs[r][d] (pad 68), Kt[d][c] (pad 68, d-major), Ss[r][c] (pad 68),
//       Vs[c][d] (stride 64).
// ---------------------------------------------------------------------------
__global__ __launch_bounds__(256)
void attn_kernel(const float* __restrict__ Qh, const float* __restrict__ Kh,
                 const float* __restrict__ Vh, const float* __restrict__ structure,
                 float* __restrict__ ctx) {
    extern __shared__ float sm[];
    float* Qs = sm;                 // 64*68
    float* Kt = Qs + 64 * 68;       // 64*68
    float* Ss = Kt + 64 * 68;       // 64*68
    float* Vs = Ss + 64 * 68;       // 64*64

    const int tid = threadIdx.x;
    const int ty = tid >> 4;
    const int tx = tid & 15;
    const int q0 = blockIdx.x * 64;
    const int h = blockIdx.y;
    const int b = blockIdx.z;
    const size_t baseQ = ((size_t)b * SS + q0) * DD + h * 64;

    // Load Q tile [64 x 64]
#pragma unroll
    for (int t = 0; t < 4; t++) {
        int idx = tid + t * 256;
        int r = idx >> 4, d4 = idx & 15;
        float4 v = *reinterpret_cast<const float4*>(Qh + baseQ + (size_t)r * DD + d4 * 4);
        *reinterpret_cast<float4*>(&Qs[r * 68 + d4 * 4]) = v;
    }

    float m_i[4], l_i[4], acc[4][4];
#pragma unroll
    for (int i = 0; i < 4; i++) {
        m_i[i] = -1e30f;
        l_i[i] = 0.0f;
#pragma unroll
        for (int j = 0; j < 4; j++) acc[i][j] = 0.0f;
    }
    const float scale = 0.125f;  // 1/sqrt(64)

    for (int kt = 0; kt < SS / 64; kt++) {
        const int k0 = kt * 64;
        const size_t baseK = ((size_t)b * SS + k0) * DD + h * 64;
        __syncthreads();  // guard Kt/Vs/Ss reuse (and Qs on first iter)

        // Load V tile natural [c][d]
#pragma unroll
        for (int t = 0; t < 4; t++) {
            int idx = tid + t * 256;
            int c = idx >> 4, d4 = idx & 15;
            float4 v = *reinterpret_cast<const float4*>(Vh + baseK + (size_t)c * DD + d4 * 4);
            *reinterpret_cast<float4*>(&Vs[c * 64 + d4 * 4]) = v;
        }
        // Load K tile transposed into Kt[d][c] (mapping chosen for
        // conflict-free STS; global reads become 16B/row gathers, L2-resident)
#pragma unroll
        for (int t = 0; t < 4; t++) {
            int idx = tid + t * 256;
            int d4 = idx >> 6, c = idx & 63;
            float4 kv = *reinterpret_cast<const float4*>(Kh + baseK + (size_t)c * DD + d4 * 4);
            Kt[(d4 * 4 + 0) * 68 + c] = kv.x;
            Kt[(d4 * 4 + 1) * 68 + c] = kv.y;
            Kt[(d4 * 4 + 2) * 68 + c] = kv.z;
            Kt[(d4 * 4 + 3) * 68 + c] = kv.w;
        }
        __syncthreads();

        // Scores: s[i][j] = sum_d Q[r][d] * K[c][d]
        float s[4][4];
#pragma unroll
        for (int i = 0; i < 4; i++)
#pragma unroll
            for (int j = 0; j < 4; j++) s[i][j] = 0.0f;

#pragma unroll 8
        for (int d = 0; d < 64; d++) {
            float4 kk = *reinterpret_cast<const float4*>(&Kt[d * 68 + tx * 4]);
            float rq[4];
#pragma unroll
            for (int i = 0; i < 4; i++) rq[i] = Qs[(ty * 4 + i) * 68 + d];
#pragma unroll
            for (int i = 0; i < 4; i++) {
                s[i][0] += rq[i] * kk.x;
                s[i][1] += rq[i] * kk.y;
                s[i][2] += rq[i] * kk.z;
                s[i][3] += rq[i] * kk.w;
            }
        }

        // Scale + structural bias + online softmax update
#pragma unroll
        for (int i = 0; i < 4; i++) {
            const float4 st = *reinterpret_cast<const float4*>(
                structure + ((size_t)b * SS + q0 + ty * 4 + i) * SS + k0 + tx * 4);
            s[i][0] = s[i][0] * scale + st.x;
            s[i][1] = s[i][1] * scale + st.y;
            s[i][2] = s[i][2] * scale + st.z;
            s[i][3] = s[i][3] * scale + st.w;

            float tm = fmaxf(fmaxf(s[i][0], s[i][1]), fmaxf(s[i][2], s[i][3]));
            tm = fmaxf(tm, __shfl_xor_sync(0xffffffffu, tm, 1));
            tm = fmaxf(tm, __shfl_xor_sync(0xffffffffu, tm, 2));
            tm = fmaxf(tm, __shfl_xor_sync(0xffffffffu, tm, 4));
            tm = fmaxf(tm, __shfl_xor_sync(0xffffffffu, tm, 8));

            float mn = fmaxf(m_i[i], tm);
            float al = __expf(m_i[i] - mn);
            s[i][0] = __expf(s[i][0] - mn);
            s[i][1] = __expf(s[i][1] - mn);
            s[i][2] = __expf(s[i][2] - mn);
            s[i][3] = __expf(s[i][3] - mn);
            float rs = s[i][0] + s[i][1] + s[i][2] + s[i][3];
            rs += __shfl_xor_sync(0xffffffffu, rs, 1);
            rs += __shfl_xor_sync(0xffffffffu, rs, 2);
            rs += __shfl_xor_sync(0xffffffffu, rs, 4);
            rs += __shfl_xor_sync(0xffffffffu, rs, 8);

            l_i[i] = l_i[i] * al + rs;
            m_i[i] = mn;
#pragma unroll
            for (int j = 0; j < 4; j++) acc[i][j] *= al;

            *reinterpret_cast<float4*>(&Ss[(ty * 4 + i) * 68 + tx * 4]) =
                make_float4(s[i][0], s[i][1], s[i][2], s[i][3]);
        }
        __syncthreads();

        // PV: acc[i][j] += sum_c P[r][c] * V[c][d]
#pragma unroll 8
        for (int c = 0; c < 64; c++) {
            float4 vv = *reinterpret_cast<const float4*>(&Vs[c * 64 + tx * 4]);
            float rp[4];
#pragma unroll
            for (int i = 0; i < 4; i++) rp[i] = Ss[(ty * 4 + i) * 68 + c];
#pragma unroll
            for (int i = 0; i < 4; i++) {
                acc[i][0] += rp[i] * vv.x;
                acc[i][1] += rp[i] * vv.y;
                acc[i][2] += rp[i] * vv.z;
                acc[i][3] += rp[i] * vv.w;
            }
        }
    }

    // Epilogue: normalize and write ctx[b, q, h*64 + d]
#pragma unroll
    for (int i = 0; i < 4; i++) {
        float inv = 1.0f / l_i[i];
        float4 o = make_float4(acc[i][0] * inv, acc[i][1] * inv,
                               acc[i][2] * inv, acc[i][3] * inv);
        *reinterpret_cast<float4*>(ctx + baseQ + (size_t)(ty * 4 + i) * DD + tx * 4) = o;
    }
}

// ---------------------------------------------------------------------------
// kernel_launch: 3 projection GEMMs -> fused attention -> output GEMM
// ---------------------------------------------------------------------------
extern "C" void kernel_launch(void* const* d_in, const int* in_sizes, int n_in,
                              void* d_out, int out_size) {
    const float* q   = (const float*)d_in[0];
    const float* k   = (const float*)d_in[1];
    const float* v   = (const float*)d_in[2];
    const float* str = (const float*)d_in[3];
    const float* Wq  = (const float*)d_in[4];
    const float* bq  = (const float*)d_in[5];
    const float* Wk  = (const float*)d_in[6];
    const float* bk  = (const float*)d_in[7];
    const float* Wv  = (const float*)d_in[8];
    const float* bv  = (const float*)d_in[9];
    const float* Wo  = (const float*)d_in[10];
    const float* bo  = (const float*)d_in[11];
    float* out = (float*)d_out;

    float *Qh, *Kh, *Vh, *Ctx;
    cudaGetSymbolAddress((void**)&Qh, g_Qh);
    cudaGetSymbolAddress((void**)&Kh, g_Kh);
    cudaGetSymbolAddress((void**)&Vh, g_Vh);
    cudaGetSymbolAddress((void**)&Ctx, g_ctx);

    const int M = BB * SS;   // 4096
    const int N = DD;        // 512
    const int K = DD;        // 512
    dim3 gemm_grid(M / 128, N / 64);

    gemm_bias_kernel<<<gemm_grid, 256>>>(q, Wq, bq, Qh, M, N, K);
    gemm_bias_kernel<<<gemm_grid, 256>>>(k, Wk, bk, Kh, M, N, K);
    gemm_bias_kernel<<<gemm_grid, 256>>>(v, Wv, bv, Vh, M, N, K);

    const int att_smem = (64 * 68 * 3 + 64 * 64) * (int)sizeof(float);  // 68608 B
    cudaFuncSetAttribute(attn_kernel, cudaFuncAttributeMaxDynamicSharedMemorySize,
                         att_smem);
    dim3 att_grid(SS / 64, HH, BB);
    attn_kernel<<<att_grid, 256, att_smem>>>(Qh, Kh, Vh, str, Ctx);

    gemm_bias_kernel<<<gemm_grid, 256>>>(Ctx, Wo, bo, out, M, N, K);
}

// round 2
// speedup vs baseline: 1.0954x; 1.0954x over previous
#include <cuda_runtime.h>

#define BB 2
#define SS 2048
#define DD 512
#define HH 8

// Scratch (allocation-free: __device__ globals)
__device__ float g_Qh[BB * SS * DD];
__device__ float g_Kh[BB * SS * DD];
__device__ float g_Vh[BB * SS * DD];
__device__ float g_ctx[BB * SS * DD];

// ---------------------------------------------------------------------------
// GEMM: C[M,N] = A[M,K] @ W[K,N] + bias[N]
// BM=128, BN=128, BK=16. 256 threads (16x16), 8x8 micro-tile.
// A tile transposed in smem; register-staged prefetch of the next K-slab.
// ---------------------------------------------------------------------------
__global__ __launch_bounds__(256)
void gemm_bias_kernel(const float* __restrict__ A, const float* __restrict__ W,
                      const float* __restrict__ bias, float* __restrict__ C,
                      int M, int N, int K) {
    __shared__ float As[16][132];   // As[k][m]
    __shared__ float Ws[16][128];   // Ws[k][n]

    const int tid = threadIdx.x;
    const int ty = tid >> 4;        // 8 rows each
    const int tx = tid & 15;        // 8 cols each
    const int m0 = blockIdx.x * 128;
    const int n0 = blockIdx.y * 128;

    // Load indices (2 float4 each for A and W per thread)
    // A: idx = tid + t*256 -> r = idx>>2 (0..127), k4 = idx&3
    // W: idx = tid + t*256 -> kk = idx>>5 (0..15), c4 = idx&31

    float acc[8][8];
    const float4 b0 = *reinterpret_cast<const float4*>(bias + n0 + tx * 8);
    const float4 b1 = *reinterpret_cast<const float4*>(bias + n0 + tx * 8 + 4);
#pragma unroll
    for (int i = 0; i < 8; i++) {
        acc[i][0] = b0.x; acc[i][1] = b0.y; acc[i][2] = b0.z; acc[i][3] = b0.w;
        acc[i][4] = b1.x; acc[i][5] = b1.y; acc[i][6] = b1.z; acc[i][7] = b1.w;
    }

    float4 pa[2], pw[2];
    // preload k0 = 0
#pragma unroll
    for (int t = 0; t < 2; t++) {
        int idx = tid + t * 256;
        int r = idx >> 2, k4 = idx & 3;
        pa[t] = *reinterpret_cast<const float4*>(A + (size_t)(m0 + r) * K + k4 * 4);
        int kk = idx >> 5, c4 = idx & 31;
        pw[t] = *reinterpret_cast<const float4*>(W + (size_t)kk * N + n0 + c4 * 4);
    }

    for (int k0 = 0; k0 < K; k0 += 16) {
        __syncthreads();  // previous compute done before overwrite
#pragma unroll
        for (int t = 0; t < 2; t++) {
            int idx = tid + t * 256;
            int r = idx >> 2, k4 = idx & 3;
            As[k4 * 4 + 0][r] = pa[t].x;
            As[k4 * 4 + 1][r] = pa[t].y;
            As[k4 * 4 + 2][r] = pa[t].z;
            As[k4 * 4 + 3][r] = pa[t].w;
            int kk = idx >> 5, c4 = idx & 31;
            *reinterpret_cast<float4*>(&Ws[kk][c4 * 4]) = pw[t];
        }
        __syncthreads();

        // prefetch next slab (overlaps with compute below)
        if (k0 + 16 < K) {
#pragma unroll
            for (int t = 0; t < 2; t++) {
                int idx = tid + t * 256;
                int r = idx >> 2, k4 = idx & 3;
                pa[t] = *reinterpret_cast<const float4*>(
                    A + (size_t)(m0 + r) * K + k0 + 16 + k4 * 4);
                int kk = idx >> 5, c4 = idx & 31;
                pw[t] = *reinterpret_cast<const float4*>(
                    W + (size_t)(k0 + 16 + kk) * N + n0 + c4 * 4);
            }
        }

#pragma unroll
        for (int k = 0; k < 16; k++) {
            float4 a0 = *reinterpret_cast<const float4*>(&As[k][ty * 8]);
            float4 a1 = *reinterpret_cast<const float4*>(&As[k][ty * 8 + 4]);
            float4 w0 = *reinterpret_cast<const float4*>(&Ws[k][tx * 8]);
            float4 w1 = *reinterpret_cast<const float4*>(&Ws[k][tx * 8 + 4]);
            float ra[8] = {a0.x, a0.y, a0.z, a0.w, a1.x, a1.y, a1.z, a1.w};
            float rb[8] = {w0.x, w0.y, w0.z, w0.w, w1.x, w1.y, w1.z, w1.w};
#pragma unroll
            for (int i = 0; i < 8; i++)
#pragma unroll
                for (int j = 0; j < 8; j++)
                    acc[i][j] += ra[i] * rb[j];
        }
    }

#pragma unroll
    for (int i = 0; i < 8; i++) {
        float4 o0 = make_float4(acc[i][0], acc[i][1], acc[i][2], acc[i][3]);
        float4 o1 = make_float4(acc[i][4], acc[i][5], acc[i][6], acc[i][7]);
        float* cp = C + (size_t)(m0 + ty * 8 + i) * N + n0 + tx * 8;
        *reinterpret_cast<float4*>(cp) = o0;
        *reinterpret_cast<float4*>(cp + 4) = o1;
    }
}

// ---------------------------------------------------------------------------
// Fused flash attention with structural bias.
// Block = (q-tile of 128 rows, head h, batch b). 256 threads (16x16).
// Thread (ty,tx): 8 q-rows x 4 cols micro-tile. All inner-loop operands are
// LDS.128: Q stored transposed Qt[d][r], K transposed Kt[d][c], P stored
// transposed St[c][r], V natural Vs[c][d].
// Structure bias folded into score init: s = bias/scale, final s *= scale.
// ---------------------------------------------------------------------------
__global__ __launch_bounds__(256, 2)
void attn_kernel(const float* __restrict__ Qh, const float* __restrict__ Kh,
                 const float* __restrict__ Vh, const float* __restrict__ structure,
                 float* __restrict__ ctx) {
    extern __shared__ float smf[];
    float* Qt = smf;                 // [64][132]  Qt[d][r]
    float* Kt = Qt + 64 * 132;       // [64][68]   Kt[d][c]
    float* St = Kt + 64 * 68;        // [64][132]  St[c][r]
    float* Vs = St + 64 * 132;       // [64][64]   Vs[c][d]

    const int tid = threadIdx.x;
    const int ty = tid >> 4;         // 8 rows each
    const int tx = tid & 15;         // 4 cols each
    const int q0 = blockIdx.x * 128;
    const int h = blockIdx.y;
    const int b = blockIdx.z;
    const size_t baseQ = ((size_t)b * SS + q0) * DD + h * 64;

    // Load Q tile [128 x 64] transposed into Qt[d][r]
#pragma unroll
    for (int t = 0; t < 8; t++) {
        int idx = tid + t * 256;
        int r = idx >> 4, d4 = idx & 15;
        float4 qv = *reinterpret_cast<const float4*>(Qh + baseQ + (size_t)r * DD + d4 * 4);
        Qt[(d4 * 4 + 0) * 132 + r] = qv.x;
        Qt[(d4 * 4 + 1) * 132 + r] = qv.y;
        Qt[(d4 * 4 + 2) * 132 + r] = qv.z;
        Qt[(d4 * 4 + 3) * 132 + r] = qv.w;
    }

    float m_i[8], l_i[8], acc[8][4];
#pragma unroll
    for (int i = 0; i < 8; i++) {
        m_i[i] = -1e30f;
        l_i[i] = 0.0f;
#pragma unroll
        for (int j = 0; j < 4; j++) acc[i][j] = 0.0f;
    }
    const float scale = 0.125f;       // 1/sqrt(64)
    const float inv_scale = 8.0f;

    for (int kt = 0; kt < SS / 64; kt++) {
        const int k0 = kt * 64;
        const size_t baseK = ((size_t)b * SS + k0) * DD + h * 64;

        // Init scores from structure bias (pre-divided by scale); the LDG
        // latency hides under the K/V tile loads below.
        float s[8][4];
#pragma unroll
        for (int i = 0; i < 8; i++) {
            const float4 st = *reinterpret_cast<const float4*>(
                structure + ((size_t)b * SS + q0 + ty * 8 + i) * SS + k0 + tx * 4);
            s[i][0] = st.x * inv_scale;
            s[i][1] = st.y * inv_scale;
            s[i][2] = st.z * inv_scale;
            s[i][3] = st.w * inv_scale;
        }

        __syncthreads();  // previous PV reads of Kt/Vs/St done (and Qt write, iter 0)

        // V tile natural [c][d] (4 float4 per thread)
#pragma unroll
        for (int t = 0; t < 4; t++) {
            int idx = tid + t * 256;
            int c = idx >> 4, d4 = idx & 15;
            float4 vv = *reinterpret_cast<const float4*>(Vh + baseK + (size_t)c * DD + d4 * 4);
            *reinterpret_cast<float4*>(&Vs[c * 64 + d4 * 4]) = vv;
        }
        // K tile transposed into Kt[d][c]
#pragma unroll
        for (int t = 0; t < 4; t++) {
            int idx = tid + t * 256;
            int d4 = idx >> 6, c = idx & 63;
            float4 kv = *reinterpret_cast<const float4*>(Kh + baseK + (size_t)c * DD + d4 * 4);
            Kt[(d4 * 4 + 0) * 68 + c] = kv.x;
            Kt[(d4 * 4 + 1) * 68 + c] = kv.y;
            Kt[(d4 * 4 + 2) * 68 + c] = kv.z;
            Kt[(d4 * 4 + 3) * 68 + c] = kv.w;
        }
        __syncthreads();

        // Scores: s[i][j] += sum_d Q[r][d] * K[c][d]   (3 LDS.128 / 32 FMA)
#pragma unroll 4
        for (int d = 0; d < 64; d++) {
            float4 qa = *reinterpret_cast<const float4*>(&Qt[d * 132 + ty * 8]);
            float4 qb = *reinterpret_cast<const float4*>(&Qt[d * 132 + ty * 8 + 4]);
            float4 kk = *reinterpret_cast<const float4*>(&Kt[d * 68 + tx * 4]);
            float rq[8] = {qa.x, qa.y, qa.z, qa.w, qb.x, qb.y, qb.z, qb.w};
#pragma unroll
            for (int i = 0; i < 8; i++) {
                s[i][0] += rq[i] * kk.x;
                s[i][1] += rq[i] * kk.y;
                s[i][2] += rq[i] * kk.z;
                s[i][3] += rq[i] * kk.w;
            }
        }

        // Online softmax (per q-row, reduced across the 16 tx lanes)
#pragma unroll
        for (int i = 0; i < 8; i++) {
            s[i][0] *= scale; s[i][1] *= scale; s[i][2] *= scale; s[i][3] *= scale;

            float tm = fmaxf(fmaxf(s[i][0], s[i][1]), fmaxf(s[i][2], s[i][3]));
            tm = fmaxf(tm, __shfl_xor_sync(0xffffffffu, tm, 1));
            tm = fmaxf(tm, __shfl_xor_sync(0xffffffffu, tm, 2));
            tm = fmaxf(tm, __shfl_xor_sync(0xffffffffu, tm, 4));
            tm = fmaxf(tm, __shfl_xor_sync(0xffffffffu, tm, 8));

            float mn = fmaxf(m_i[i], tm);
            float al = __expf(m_i[i] - mn);
            s[i][0] = __expf(s[i][0] - mn);
            s[i][1] = __expf(s[i][1] - mn);
            s[i][2] = __expf(s[i][2] - mn);
            s[i][3] = __expf(s[i][3] - mn);
            float rs = s[i][0] + s[i][1] + s[i][2] + s[i][3];
            rs += __shfl_xor_sync(0xffffffffu, rs, 1);
            rs += __shfl_xor_sync(0xffffffffu, rs, 2);
            rs += __shfl_xor_sync(0xffffffffu, rs, 4);
            rs += __shfl_xor_sync(0xffffffffu, rs, 8);

            l_i[i] = l_i[i] * al + rs;
            m_i[i] = mn;
#pragma unroll
            for (int j = 0; j < 4; j++) acc[i][j] *= al;
        }

        // Store P transposed: St[c][r]
#pragma unroll
        for (int j = 0; j < 4; j++) {
            *reinterpret_cast<float4*>(&St[(tx * 4 + j) * 132 + ty * 8]) =
                make_float4(s[0][j], s[1][j], s[2][j], s[3][j]);
            *reinterpret_cast<float4*>(&St[(tx * 4 + j) * 132 + ty * 8 + 4]) =
                make_float4(s[4][j], s[5][j], s[6][j], s[7][j]);
        }
        __syncthreads();

        // PV: acc[i][j] += sum_c P[r][c] * V[c][d]   (3 LDS.128 / 32 FMA)
#pragma unroll 4
        for (int c = 0; c < 64; c++) {
            float4 p0 = *reinterpret_cast<const float4*>(&St[c * 132 + ty * 8]);
            float4 p1 = *reinterpret_cast<const float4*>(&St[c * 132 + ty * 8 + 4]);
            float4 vv = *reinterpret_cast<const float4*>(&Vs[c * 64 + tx * 4]);
            float rp[8] = {p0.x, p0.y, p0.z, p0.w, p1.x, p1.y, p1.z, p1.w};
#pragma unroll
            for (int i = 0; i < 8; i++) {
                acc[i][0] += rp[i] * vv.x;
                acc[i][1] += rp[i] * vv.y;
                acc[i][2] += rp[i] * vv.z;
                acc[i][3] += rp[i] * vv.w;
            }
        }
    }

    // Epilogue: normalize and write ctx[b, q, h*64 + d]
#pragma unroll
    for (int i = 0; i < 8; i++) {
        float inv = 1.0f / l_i[i];
        float4 o = make_float4(acc[i][0] * inv, acc[i][1] * inv,
                               acc[i][2] * inv, acc[i][3] * inv);
        *reinterpret_cast<float4*>(ctx + baseQ + (size_t)(ty * 8 + i) * DD + tx * 4) = o;
    }
}

// ---------------------------------------------------------------------------
// kernel_launch: 3 projection GEMMs -> fused attention -> output GEMM
// ---------------------------------------------------------------------------
extern "C" void kernel_launch(void* const* d_in, const int* in_sizes, int n_in,
                              void* d_out, int out_size) {
    const float* q   = (const float*)d_in[0];
    const float* k   = (const float*)d_in[1];
    const float* v   = (const float*)d_in[2];
    const float* str = (const float*)d_in[3];
    const float* Wq  = (const float*)d_in[4];
    const float* bq  = (const float*)d_in[5];
    const float* Wk  = (const float*)d_in[6];
    const float* bk  = (const float*)d_in[7];
    const float* Wv  = (const float*)d_in[8];
    const float* bv  = (const float*)d_in[9];
    const float* Wo  = (const float*)d_in[10];
    const float* bo  = (const float*)d_in[11];
    float* out = (float*)d_out;

    float *Qh, *Kh, *Vh, *Ctx;
    cudaGetSymbolAddress((void**)&Qh, g_Qh);
    cudaGetSymbolAddress((void**)&Kh, g_Kh);
    cudaGetSymbolAddress((void**)&Vh, g_Vh);
    cudaGetSymbolAddress((void**)&Ctx, g_ctx);

    const int M = BB * SS;   // 4096
    const int N = DD;        // 512
    const int K = DD;        // 512
    dim3 gemm_grid(M / 128, N / 128);   // 32 x 4 = 128 CTAs (single wave)

    gemm_bias_kernel<<<gemm_grid, 256>>>(q, Wq, bq, Qh, M, N, K);
    gemm_bias_kernel<<<gemm_grid, 256>>>(k, Wk, bk, Kh, M, N, K);
    gemm_bias_kernel<<<gemm_grid, 256>>>(v, Wv, bv, Vh, M, N, K);

    const int att_smem = (64 * 132 + 64 * 68 + 64 * 132 + 64 * 64) * (int)sizeof(float);
    cudaFuncSetAttribute(attn_kernel, cudaFuncAttributeMaxDynamicSharedMemorySize,
                         att_smem);
    dim3 att_grid(SS / 128, HH, BB);    // 16 x 8 x 2 = 256 CTAs
    attn_kernel<<<att_grid, 256, att_smem>>>(Qh, Kh, Vh, str, Ctx);

    gemm_bias_kernel<<<gemm_grid, 256>>>(Ctx, Wo, bo, out, M, N, K);
}